// round 1
// baseline (speedup 1.0000x reference)
#include <cuda_runtime.h>
#include <cuda_bf16.h>
#include <math_constants.h>

// Problem: B=4, T=2048, E=768, H=64
//   q = x@Wq, k = x@Wk, v = x@Wv          ([8192,768] x [768,64])
//   S = q k^T  (causal mask -> -inf, then * 1/sqrt(768))  == prescale q
//   P = softmax(S); out = P v   (fp32 out [B,T,H])

#define BATCH 4
#define SEQ   2048
#define EMB   768
#define HDIM  64
#define ROWS  (BATCH*SEQ)   // 8192

// scratch (allocation-free rule: __device__ globals)
__device__ float g_q[ROWS*HDIM];
__device__ float g_k[ROWS*HDIM];
__device__ float g_v[ROWS*HDIM];

// ---------------------------------------------------------------------------
// QKV projection: C[8192,64] = A[8192,768] * W[768,64]
// 64x64x16 smem tile, 256 threads, 4x4 microtile. blockIdx.y selects weight.
// ---------------------------------------------------------------------------
__global__ __launch_bounds__(256)
void qkv_gemm(const float* __restrict__ x,
              const float* __restrict__ Wk,
              const float* __restrict__ Wq,
              const float* __restrict__ Wv)
{
    __shared__ float As[16][64];   // As[k][m]
    __shared__ float Bs[16][64];   // Bs[k][n]

    const float* W;
    float* out;
    switch (blockIdx.y) {
        case 0:  W = Wq; out = g_q; break;
        case 1:  W = Wk; out = g_k; break;
        default: W = Wv; out = g_v; break;
    }

    const int m0 = blockIdx.x * 64;
    const int t  = threadIdx.x;
    const int tx = t & 15;         // col group
    const int ty = t >> 4;         // row group

    float acc[4][4] = {};

    for (int k0 = 0; k0 < EMB; k0 += 16) {
        // load A tile: 64 rows x 16 cols (1024 floats = 256 float4)
        {
            int r = t >> 2;               // 0..63
            int c = (t & 3) << 2;         // 0,4,8,12
            float4 a = *(const float4*)(x + (size_t)(m0 + r) * EMB + k0 + c);
            As[c + 0][r] = a.x;
            As[c + 1][r] = a.y;
            As[c + 2][r] = a.z;
            As[c + 3][r] = a.w;
        }
        // load B tile: 16 rows x 64 cols
        {
            int r = t >> 4;               // 0..15
            int c = (t & 15) << 2;        // 0..60
            float4 b = *(const float4*)(W + (size_t)(k0 + r) * HDIM + c);
            *(float4*)&Bs[r][c] = b;
        }
        __syncthreads();

        #pragma unroll
        for (int kk = 0; kk < 16; kk++) {
            float a[4], b[4];
            #pragma unroll
            for (int i = 0; i < 4; i++) a[i] = As[kk][ty * 4 + i];
            #pragma unroll
            for (int j = 0; j < 4; j++) b[j] = Bs[kk][tx * 4 + j];
            #pragma unroll
            for (int i = 0; i < 4; i++)
                #pragma unroll
                for (int j = 0; j < 4; j++)
                    acc[i][j] = fmaf(a[i], b[j], acc[i][j]);
        }
        __syncthreads();
    }

    #pragma unroll
    for (int i = 0; i < 4; i++) {
        float4 v = make_float4(acc[i][0], acc[i][1], acc[i][2], acc[i][3]);
        *(float4*)(out + (size_t)(m0 + ty * 4 + i) * HDIM + tx * 4) = v;
    }
}

// ---------------------------------------------------------------------------
// Flash attention (fp32): 32 query rows per block, 64-key tiles.
// 256 threads = 8 warps; warp w owns rows w*4..w*4+3; lane owns key/out
// columns {lane, lane+32}. Online softmax; O in registers.
// smem: Qs[32][64] + Ks[64][65] + Vs[64][64] + Ps[32][64]  = 49408 B (dynamic)
// ---------------------------------------------------------------------------
#define BQ 32
#define BK 64
#define NEG_BIG (-1e30f)

extern __shared__ float smem[];

__global__ __launch_bounds__(256)
void attn_kernel(float* __restrict__ out)
{
    float* Qs = smem;                       // [32][64]   2048
    float* Ks = Qs + BQ * HDIM;             // [64][65]   4160
    float* Vs = Ks + BK * 65;               // [64][64]   4096
    float* Ps = Vs + BK * HDIM;             // [32][64]   2048

    const int b  = blockIdx.y;
    const int q0 = blockIdx.x * BQ;
    const int t    = threadIdx.x;
    const int lane = t & 31;
    const int w    = t >> 5;
    const int r0   = w * 4;                 // warp's first row (local)

    const float scale = rsqrtf((float)EMB);

    const float* Qg = g_q + ((size_t)b * SEQ + q0) * HDIM;
    // load + prescale Q: 2048 floats = 512 float4
    for (int i = t; i < (BQ * HDIM) / 4; i += 256) {
        int r = i >> 4;
        int c = (i & 15) << 2;
        float4 qv = *(const float4*)(Qg + r * HDIM + c);
        Qs[r * HDIM + c + 0] = qv.x * scale;
        Qs[r * HDIM + c + 1] = qv.y * scale;
        Qs[r * HDIM + c + 2] = qv.z * scale;
        Qs[r * HDIM + c + 3] = qv.w * scale;
    }

    float m[4], l[4], O[4][2];
    #pragma unroll
    for (int i = 0; i < 4; i++) {
        m[i] = NEG_BIG; l[i] = 0.f; O[i][0] = 0.f; O[i][1] = 0.f;
    }

    const int nkb = (q0 + BQ + BK - 1) / BK;   // key blocks to visit

    for (int kb = 0; kb < nkb; kb++) {
        const int k0 = kb * BK;
        __syncthreads();
        const float* Kg = g_k + ((size_t)b * SEQ + k0) * HDIM;
        const float* Vg = g_v + ((size_t)b * SEQ + k0) * HDIM;
        for (int i = t; i < (BK * HDIM) / 4; i += 256) {
            int r = i >> 4;
            int c = (i & 15) << 2;
            float4 kv = *(const float4*)(Kg + r * HDIM + c);
            Ks[r * 65 + c + 0] = kv.x;
            Ks[r * 65 + c + 1] = kv.y;
            Ks[r * 65 + c + 2] = kv.z;
            Ks[r * 65 + c + 3] = kv.w;
            float4 vv = *(const float4*)(Vg + r * HDIM + c);
            *(float4*)&Vs[r * HDIM + c] = vv;
        }
        __syncthreads();

        // S = Qs * Ks^T  (per-lane: 4 rows x 2 cols)
        float acc[4][2] = {};
        #pragma unroll 8
        for (int h = 0; h < HDIM; h++) {
            float k0v = Ks[lane * 65 + h];
            float k1v = Ks[(lane + 32) * 65 + h];
            #pragma unroll
            for (int i = 0; i < 4; i++) {
                float qv = Qs[(r0 + i) * HDIM + h];
                acc[i][0] = fmaf(qv, k0v, acc[i][0]);
                acc[i][1] = fmaf(qv, k1v, acc[i][1]);
            }
        }

        const bool last = (kb == nkb - 1);

        #pragma unroll
        for (int i = 0; i < 4; i++) {
            if (last) {
                int qg = q0 + r0 + i;
                if (k0 + lane      > qg) acc[i][0] = NEG_BIG;
                if (k0 + lane + 32 > qg) acc[i][1] = NEG_BIG;
            }
            // row max across warp
            float mx = fmaxf(acc[i][0], acc[i][1]);
            #pragma unroll
            for (int o = 16; o > 0; o >>= 1)
                mx = fmaxf(mx, __shfl_xor_sync(0xffffffffu, mx, o));
            float mn   = fmaxf(m[i], mx);
            float corr = __expf(m[i] - mn);
            float p0   = __expf(acc[i][0] - mn);
            float p1   = __expf(acc[i][1] - mn);
            float rs   = p0 + p1;
            #pragma unroll
            for (int o = 16; o > 0; o >>= 1)
                rs += __shfl_xor_sync(0xffffffffu, rs, o);
            l[i] = l[i] * corr + rs;
            m[i] = mn;
            O[i][0] *= corr;
            O[i][1] *= corr;
            Ps[(r0 + i) * HDIM + lane]      = p0;
            Ps[(r0 + i) * HDIM + lane + 32] = p1;
        }
        __syncwarp();

        // O += P * V
        #pragma unroll 8
        for (int s = 0; s < BK; s++) {
            float v0 = Vs[s * HDIM + lane];
            float v1 = Vs[s * HDIM + lane + 32];
            #pragma unroll
            for (int i = 0; i < 4; i++) {
                float pv = Ps[(r0 + i) * HDIM + s];
                O[i][0] = fmaf(pv, v0, O[i][0]);
                O[i][1] = fmaf(pv, v1, O[i][1]);
            }
        }
    }

    #pragma unroll
    for (int i = 0; i < 4; i++) {
        float inv = 1.0f / l[i];
        size_t row = (size_t)b * SEQ + q0 + r0 + i;
        out[row * HDIM + lane]      = O[i][0] * inv;
        out[row * HDIM + lane + 32] = O[i][1] * inv;
    }
}

// ---------------------------------------------------------------------------
extern "C" void kernel_launch(void* const* d_in, const int* in_sizes, int n_in,
                              void* d_out, int out_size)
{
    const float* x  = (const float*)d_in[0];
    const float* Wk = (const float*)d_in[1];
    const float* Wq = (const float*)d_in[2];
    const float* Wv = (const float*)d_in[3];
    float* out = (float*)d_out;

    // QKV projections
    dim3 ggrid(ROWS / 64, 3);
    qkv_gemm<<<ggrid, 256>>>(x, Wk, Wq, Wv);

    // attention
    const int smem_bytes = (BQ * HDIM + BK * 65 + BK * HDIM + BQ * HDIM) * 4; // 49408
    cudaFuncSetAttribute(attn_kernel,
                         cudaFuncAttributeMaxDynamicSharedMemorySize, smem_bytes);
    dim3 agrid(SEQ / BQ, BATCH);
    attn_kernel<<<agrid, 256, smem_bytes>>>(out);
}

// round 2
// speedup vs baseline: 1.1663x; 1.1663x over previous
#include <cuda_runtime.h>
#include <cuda_bf16.h>
#include <math_constants.h>

// B=4, T=2048, E=768, H=64
// q=x@Wq, k=x@Wk, v=x@Wv; S=qk^T (causal->-inf, then /sqrt(E)) == prescale q
// P=softmax(S); out = P v  (fp32 [B,T,H])

#define BATCH 4
#define SEQ   2048
#define EMB   768
#define HDIM  64
#define ROWS  (BATCH*SEQ)   // 8192

__device__ float g_q[ROWS*HDIM];
__device__ float g_k[ROWS*HDIM];
__device__ float g_v[ROWS*HDIM];

// ---------------------------------------------------------------------------
// QKV projection: C[8192,64] = A[8192,768] * W[768,64]
// 64x64x16 smem tile, 256 threads, 4x4 microtile, float4 LDS in microkernel.
// ---------------------------------------------------------------------------
__global__ __launch_bounds__(256)
void qkv_gemm(const float* __restrict__ x,
              const float* __restrict__ Wk,
              const float* __restrict__ Wq,
              const float* __restrict__ Wv)
{
    __shared__ float As[16][64];   // As[k][m]
    __shared__ float Bs[16][64];   // Bs[k][n]

    const float* W;
    float* out;
    switch (blockIdx.y) {
        case 0:  W = Wq; out = g_q; break;
        case 1:  W = Wk; out = g_k; break;
        default: W = Wv; out = g_v; break;
    }

    const int m0 = blockIdx.x * 64;
    const int t  = threadIdx.x;
    const int tx = t & 15;
    const int ty = t >> 4;

    float acc[4][4] = {};

    for (int k0 = 0; k0 < EMB; k0 += 16) {
        {
            int r = t >> 2;
            int c = (t & 3) << 2;
            float4 a = *(const float4*)(x + (size_t)(m0 + r) * EMB + k0 + c);
            As[c + 0][r] = a.x;
            As[c + 1][r] = a.y;
            As[c + 2][r] = a.z;
            As[c + 3][r] = a.w;
        }
        {
            int r = t >> 4;
            int c = (t & 15) << 2;
            *(float4*)&Bs[r][c] = *(const float4*)(W + (size_t)(k0 + r) * HDIM + c);
        }
        __syncthreads();

        #pragma unroll
        for (int kk = 0; kk < 16; kk++) {
            float4 a = *(const float4*)&As[kk][ty * 4];
            float4 b = *(const float4*)&Bs[kk][tx * 4];
            const float av[4] = {a.x, a.y, a.z, a.w};
            const float bv[4] = {b.x, b.y, b.z, b.w};
            #pragma unroll
            for (int i = 0; i < 4; i++)
                #pragma unroll
                for (int j = 0; j < 4; j++)
                    acc[i][j] = fmaf(av[i], bv[j], acc[i][j]);
        }
        __syncthreads();
    }

    #pragma unroll
    for (int i = 0; i < 4; i++) {
        float4 v = make_float4(acc[i][0], acc[i][1], acc[i][2], acc[i][3]);
        *(float4*)(out + (size_t)(m0 + ty * 4 + i) * HDIM + tx * 4) = v;
    }
}

// ---------------------------------------------------------------------------
// Flash attention (fp32), causal-balanced: each CTA processes q-tiles
// {pid, 63-pid} sequentially -> uniform ~34 key-block visits per CTA.
// 256 thr = 8 warps; warp w owns rows w*4..w*4+3; lane owns cols {lane,lane+32}.
// All hot smem reads are float4; K/V/P rows padded to stride 68 (17 odd ->
// conflict-free 8-lane LDS.128 phases).
// ---------------------------------------------------------------------------
#define BQ   32
#define BK   64
#define KSTR 68
#define VSTR 68
#define PSTR 68
#define NEG_BIG (-1e30f)

extern __shared__ float smem[];

__global__ __launch_bounds__(256)
void attn_kernel(float* __restrict__ out)
{
    float* Qs = smem;                       // [32][64]
    float* Ks = Qs + BQ * HDIM;             // [64][68]
    float* Vs = Ks + BK * KSTR;             // [64][68]
    float* Ps = Vs + BK * VSTR;             // [32][68]

    const int b    = blockIdx.y;
    const int pid  = blockIdx.x;            // 0..31
    const int t    = threadIdx.x;
    const int lane = t & 31;
    const int w    = t >> 5;
    const int r0   = w * 4;

    const float scale = rsqrtf((float)EMB);

    #pragma unroll
    for (int tt = 0; tt < 2; tt++) {
        const int tile = tt == 0 ? pid : 63 - pid;
        const int q0   = tile * BQ;

        __syncthreads();   // protect Qs/Ks/Vs/Ps from previous tile's readers

        // load + prescale Q
        const float* Qg = g_q + ((size_t)b * SEQ + q0) * HDIM;
        for (int i = t; i < (BQ * HDIM) / 4; i += 256) {
            int r = i >> 4;
            int c = (i & 15) << 2;
            float4 qv = *(const float4*)(Qg + r * HDIM + c);
            qv.x *= scale; qv.y *= scale; qv.z *= scale; qv.w *= scale;
            *(float4*)&Qs[r * HDIM + c] = qv;
        }

        float m[4], l[4], O[4][2];
        #pragma unroll
        for (int i = 0; i < 4; i++) {
            m[i] = NEG_BIG; l[i] = 0.f; O[i][0] = 0.f; O[i][1] = 0.f;
        }

        const int nkb = (q0 + BQ + BK - 1) / BK;

        for (int kb = 0; kb < nkb; kb++) {
            const int k0 = kb * BK;
            __syncthreads();
            const float* Kg = g_k + ((size_t)b * SEQ + k0) * HDIM;
            const float* Vg = g_v + ((size_t)b * SEQ + k0) * HDIM;
            for (int i = t; i < (BK * HDIM) / 4; i += 256) {
                int r = i >> 4;
                int c = (i & 15) << 2;
                *(float4*)&Ks[r * KSTR + c] = *(const float4*)(Kg + r * HDIM + c);
                *(float4*)&Vs[r * VSTR + c] = *(const float4*)(Vg + r * HDIM + c);
            }
            __syncthreads();

            // ---- S = Q K^T : per lane 4 rows x 2 key-cols, float4 over h ----
            float acc[4][2] = {};
            #pragma unroll
            for (int h = 0; h < HDIM; h += 4) {
                float4 k0v = *(const float4*)&Ks[lane * KSTR + h];
                float4 k1v = *(const float4*)&Ks[(lane + 32) * KSTR + h];
                #pragma unroll
                for (int i = 0; i < 4; i++) {
                    float4 qv = *(const float4*)&Qs[(r0 + i) * HDIM + h];
                    acc[i][0] = fmaf(qv.x, k0v.x,
                                fmaf(qv.y, k0v.y,
                                fmaf(qv.z, k0v.z,
                                fmaf(qv.w, k0v.w, acc[i][0]))));
                    acc[i][1] = fmaf(qv.x, k1v.x,
                                fmaf(qv.y, k1v.y,
                                fmaf(qv.z, k1v.z,
                                fmaf(qv.w, k1v.w, acc[i][1]))));
                }
            }

            const bool last = (kb == nkb - 1);

            #pragma unroll
            for (int i = 0; i < 4; i++) {
                if (last) {
                    int qg = q0 + r0 + i;
                    if (k0 + lane      > qg) acc[i][0] = NEG_BIG;
                    if (k0 + lane + 32 > qg) acc[i][1] = NEG_BIG;
                }
                float mx = fmaxf(acc[i][0], acc[i][1]);
                #pragma unroll
                for (int o = 16; o > 0; o >>= 1)
                    mx = fmaxf(mx, __shfl_xor_sync(0xffffffffu, mx, o));
                float mn   = fmaxf(m[i], mx);
                float corr = __expf(m[i] - mn);
                float p0   = __expf(acc[i][0] - mn);
                float p1   = __expf(acc[i][1] - mn);
                float rs   = p0 + p1;
                #pragma unroll
                for (int o = 16; o > 0; o >>= 1)
                    rs += __shfl_xor_sync(0xffffffffu, rs, o);
                l[i] = l[i] * corr + rs;
                m[i] = mn;
                O[i][0] *= corr;
                O[i][1] *= corr;
                Ps[(r0 + i) * PSTR + lane]      = p0;
                Ps[(r0 + i) * PSTR + lane + 32] = p1;
            }
            __syncwarp();

            // ---- O += P V : float4 over s for P, scalar V ----
            #pragma unroll
            for (int s4 = 0; s4 < BK; s4 += 4) {
                float4 pr[4];
                #pragma unroll
                for (int i = 0; i < 4; i++)
                    pr[i] = *(const float4*)&Ps[(r0 + i) * PSTR + s4];
                #pragma unroll
                for (int u = 0; u < 4; u++) {
                    float v0 = Vs[(s4 + u) * VSTR + lane];
                    float v1 = Vs[(s4 + u) * VSTR + lane + 32];
                    #pragma unroll
                    for (int i = 0; i < 4; i++) {
                        float pv = ((const float*)&pr[i])[u];
                        O[i][0] = fmaf(pv, v0, O[i][0]);
                        O[i][1] = fmaf(pv, v1, O[i][1]);
                    }
                }
            }
        }

        #pragma unroll
        for (int i = 0; i < 4; i++) {
            float inv = 1.0f / l[i];
            size_t row = (size_t)b * SEQ + q0 + r0 + i;
            out[row * HDIM + lane]      = O[i][0] * inv;
            out[row * HDIM + lane + 32] = O[i][1] * inv;
        }
    }
}

// ---------------------------------------------------------------------------
extern "C" void kernel_launch(void* const* d_in, const int* in_sizes, int n_in,
                              void* d_out, int out_size)
{
    const float* x  = (const float*)d_in[0];
    const float* Wk = (const float*)d_in[1];
    const float* Wq = (const float*)d_in[2];
    const float* Wv = (const float*)d_in[3];
    float* out = (float*)d_out;

    dim3 ggrid(ROWS / 64, 3);
    qkv_gemm<<<ggrid, 256>>>(x, Wk, Wq, Wv);

    const int smem_bytes = (BQ * HDIM + BK * KSTR + BK * VSTR + BQ * PSTR) * 4; // 51712
    cudaFuncSetAttribute(attn_kernel,
                         cudaFuncAttributeMaxDynamicSharedMemorySize, smem_bytes);
    dim3 agrid(32, BATCH);
    attn_kernel<<<agrid, 256, smem_bytes>>>(out);
}

// round 4
// speedup vs baseline: 1.6007x; 1.3725x over previous
#include <cuda_runtime.h>
#include <cuda_bf16.h>
#include <cstdint>

// B=4, T=2048, E=768, H=64 — causal single-head attention, fp32 out.
// qkv_gemm (fp32 math -> bf16 hi/lo splits) + fused flash attention on
// mma.sync.m16n8k16.bf16 (compute_103-safe; no tcgen05).

#define BATCH 4
#define SEQ   2048
#define EMB   768
#define HDIM  64
#define ROWS  (BATCH*SEQ)   // 8192

__device__ __nv_bfloat16 g_qh[ROWS*HDIM], g_ql[ROWS*HDIM];
__device__ __nv_bfloat16 g_kh[ROWS*HDIM], g_kl[ROWS*HDIM];
__device__ __nv_bfloat16 g_vh[ROWS*HDIM], g_vl[ROWS*HDIM];

// ---------------- warp-mma helpers (sm_80+ baseline PTX) --------------------
__device__ __forceinline__ void ldsm_x4(uint32_t* r, const void* p) {
    uint32_t a = (uint32_t)__cvta_generic_to_shared(p);
    asm volatile("ldmatrix.sync.aligned.m8n8.x4.shared.b16 {%0,%1,%2,%3}, [%4];"
                 : "=r"(r[0]), "=r"(r[1]), "=r"(r[2]), "=r"(r[3]) : "r"(a));
}
__device__ __forceinline__ void ldsm_x4_t(uint32_t* r, const void* p) {
    uint32_t a = (uint32_t)__cvta_generic_to_shared(p);
    asm volatile("ldmatrix.sync.aligned.m8n8.x4.trans.shared.b16 {%0,%1,%2,%3}, [%4];"
                 : "=r"(r[0]), "=r"(r[1]), "=r"(r[2]), "=r"(r[3]) : "r"(a));
}
__device__ __forceinline__ void mma16816(float* c, const uint32_t* a,
                                         uint32_t b0, uint32_t b1) {
    asm volatile("mma.sync.aligned.m16n8k16.row.col.f32.bf16.bf16.f32 "
                 "{%0,%1,%2,%3}, {%4,%5,%6,%7}, {%8,%9}, {%0,%1,%2,%3};"
                 : "+f"(c[0]), "+f"(c[1]), "+f"(c[2]), "+f"(c[3])
                 : "r"(a[0]), "r"(a[1]), "r"(a[2]), "r"(a[3]), "r"(b0), "r"(b1));
}
__device__ __forceinline__ uint32_t pack_bf16x2(float lo, float hi) {
    uint32_t r;
    asm("cvt.rn.bf16x2.f32 %0, %1, %2;" : "=r"(r) : "f"(hi), "f"(lo));
    return r;
}
// split (p0,p1) into bf16x2 hi + bf16x2 lo (residual)
__device__ __forceinline__ void split2(float p0, float p1, uint32_t& hi, uint32_t& lo) {
    uint32_t h = pack_bf16x2(p0, p1);
    __nv_bfloat162 hb = *reinterpret_cast<__nv_bfloat162*>(&h);
    float2 hf = __bfloat1622float2(hb);
    lo = pack_bf16x2(p0 - hf.x, p1 - hf.y);
    hi = h;
}

// ---------------------------------------------------------------------------
// K1: QKV projection (fp32 math), epilogue writes bf16 hi/lo splits (Q scaled).
// ---------------------------------------------------------------------------
__global__ __launch_bounds__(256)
void qkv_gemm(const float* __restrict__ x,
              const float* __restrict__ Wk,
              const float* __restrict__ Wq,
              const float* __restrict__ Wv)
{
    __shared__ float As[16][64];
    __shared__ float Bs[16][64];

    const float* W = (blockIdx.y == 0) ? Wq : (blockIdx.y == 1) ? Wk : Wv;

    const int m0 = blockIdx.x * 64;
    const int t  = threadIdx.x;
    const int tx = t & 15;
    const int ty = t >> 4;

    float acc[4][4] = {};

    for (int k0 = 0; k0 < EMB; k0 += 16) {
        {
            int r = t >> 2, c = (t & 3) << 2;
            float4 a = *(const float4*)(x + (size_t)(m0 + r) * EMB + k0 + c);
            As[c + 0][r] = a.x; As[c + 1][r] = a.y;
            As[c + 2][r] = a.z; As[c + 3][r] = a.w;
        }
        {
            int r = t >> 4, c = (t & 15) << 2;
            *(float4*)&Bs[r][c] = *(const float4*)(W + (size_t)(k0 + r) * HDIM + c);
        }
        __syncthreads();
        #pragma unroll
        for (int kk = 0; kk < 16; kk++) {
            float4 a = *(const float4*)&As[kk][ty * 4];
            float4 b = *(const float4*)&Bs[kk][tx * 4];
            const float av[4] = {a.x, a.y, a.z, a.w};
            const float bv[4] = {b.x, b.y, b.z, b.w};
            #pragma unroll
            for (int i = 0; i < 4; i++)
                #pragma unroll
                for (int j = 0; j < 4; j++)
                    acc[i][j] = fmaf(av[i], bv[j], acc[i][j]);
        }
        __syncthreads();
    }

    const float sc = (blockIdx.y == 0) ? rsqrtf((float)EMB) : 1.0f;
    __nv_bfloat16* oh = (blockIdx.y == 0) ? g_qh : (blockIdx.y == 1) ? g_kh : g_vh;
    __nv_bfloat16* ol = (blockIdx.y == 0) ? g_ql : (blockIdx.y == 1) ? g_kl : g_vl;

    #pragma unroll
    for (int i = 0; i < 4; i++) {
        int row = m0 + ty * 4 + i;
        #pragma unroll
        for (int j = 0; j < 4; j += 2) {
            float v0 = acc[i][j] * sc, v1 = acc[i][j + 1] * sc;
            __nv_bfloat162 hp = __floats2bfloat162_rn(v0, v1);
            float2 hf = __bfloat1622float2(hp);
            __nv_bfloat162 lp = __floats2bfloat162_rn(v0 - hf.x, v1 - hf.y);
            *(__nv_bfloat162*)&oh[(size_t)row * HDIM + tx * 4 + j] = hp;
            *(__nv_bfloat162*)&ol[(size_t)row * HDIM + tx * 4 + j] = lp;
        }
    }
}

// ---------------------------------------------------------------------------
// K2: fused flash attention. CTA = 64 q rows (4 warps x 16), BK = 64 keys.
// S = Qh Kh^T + Qh Kl^T + Ql Kh^T (fp32 accum); online softmax in frag layout;
// O = Ph Vh + Ph Vl + Pl Vh. Q frags register-resident; K/V smem, stride 72.
// ---------------------------------------------------------------------------
#define BQ  64
#define BK  64
#define STR 72
#define NEG_BIG (-1e30f)

__global__ __launch_bounds__(128)
void attn_kernel(float* __restrict__ out)
{
    __shared__ __nv_bfloat16 sKh[BK * STR], sKl[BK * STR];
    __shared__ __nv_bfloat16 sVh[BK * STR], sVl[BK * STR];

    const int b    = blockIdx.y;
    const int tile = blockIdx.x;         // 0..31
    const int q0   = tile * BQ;
    const int t    = threadIdx.x;
    const int w    = t >> 5;
    const int lane = t & 31;

    // ---- stage Q (hi/lo) into sKh/sKl, then pull A-frags into registers ----
    {
        int row = t >> 1, half = t & 1;
        size_t g = (size_t)(b * SEQ + q0 + row) * HDIM + half * 32;
        const uint4* ph = (const uint4*)(g_qh + g);
        const uint4* pl = (const uint4*)(g_ql + g);
        #pragma unroll
        for (int i = 0; i < 4; i++) {
            *(uint4*)&sKh[row * STR + half * 32 + i * 8] = ph[i];
            *(uint4*)&sKl[row * STR + half * 32 + i * 8] = pl[i];
        }
    }
    __syncthreads();

    uint32_t qhf[4][4], qlf[4][4];
    {
        int lrow = (lane & 7) + ((lane >> 3) & 1) * 8;   // 0..15
        int lcol = (lane >> 4) * 8;
        #pragma unroll
        for (int kc = 0; kc < 4; kc++) {
            ldsm_x4(qhf[kc], &sKh[(w * 16 + lrow) * STR + kc * 16 + lcol]);
            ldsm_x4(qlf[kc], &sKl[(w * 16 + lrow) * STR + kc * 16 + lcol]);
        }
    }

    float m0 = NEG_BIG, m1 = NEG_BIG, l0 = 0.f, l1 = 0.f;
    float o[8][4];
    #pragma unroll
    for (int j = 0; j < 8; j++)
        #pragma unroll
        for (int e = 0; e < 4; e++) o[j][e] = 0.f;

    const int nkb = tile + 1;

    for (int kb = 0; kb < nkb; kb++) {
        const int k0 = kb * BK;
        __syncthreads();
        {
            int row = t >> 1, half = t & 1;
            size_t g = (size_t)(b * SEQ + k0 + row) * HDIM + half * 32;
            const uint4* pkh = (const uint4*)(g_kh + g);
            const uint4* pkl = (const uint4*)(g_kl + g);
            const uint4* pvh = (const uint4*)(g_vh + g);
            const uint4* pvl = (const uint4*)(g_vl + g);
            #pragma unroll
            for (int i = 0; i < 4; i++) {
                int so = row * STR + half * 32 + i * 8;
                *(uint4*)&sKh[so] = pkh[i];
                *(uint4*)&sKl[so] = pkl[i];
                *(uint4*)&sVh[so] = pvh[i];
                *(uint4*)&sVl[so] = pvl[i];
            }
        }
        __syncthreads();

        // ---- S = Q K^T (bf16 x3) ----
        float c[8][4];
        #pragma unroll
        for (int j = 0; j < 8; j++)
            #pragma unroll
            for (int e = 0; e < 4; e++) c[j][e] = 0.f;

        #pragma unroll
        for (int kc = 0; kc < 4; kc++) {
            #pragma unroll
            for (int jp = 0; jp < 4; jp++) {
                int krow = 16 * jp + (lane & 7) + (lane >> 4) * 8;
                int kcol = kc * 16 + ((lane >> 3) & 1) * 8;
                uint32_t bh[4], bl[4];
                ldsm_x4(bh, &sKh[krow * STR + kcol]);
                ldsm_x4(bl, &sKl[krow * STR + kcol]);
                mma16816(c[2 * jp],     qhf[kc], bh[0], bh[1]);
                mma16816(c[2 * jp],     qhf[kc], bl[0], bl[1]);
                mma16816(c[2 * jp],     qlf[kc], bh[0], bh[1]);
                mma16816(c[2 * jp + 1], qhf[kc], bh[2], bh[3]);
                mma16816(c[2 * jp + 1], qhf[kc], bl[2], bl[3]);
                mma16816(c[2 * jp + 1], qlf[kc], bh[2], bh[3]);
            }
        }

        // ---- causal mask (diagonal block only) ----
        if (k0 == q0) {
            int r0g = q0 + w * 16 + (lane >> 2);
            #pragma unroll
            for (int j = 0; j < 8; j++) {
                int cg = k0 + 8 * j + 2 * (lane & 3);
                if (cg     > r0g)     c[j][0] = NEG_BIG;
                if (cg + 1 > r0g)     c[j][1] = NEG_BIG;
                if (cg     > r0g + 8) c[j][2] = NEG_BIG;
                if (cg + 1 > r0g + 8) c[j][3] = NEG_BIG;
            }
        }

        // ---- online softmax (rows: lane>>2 and lane>>2 + 8) ----
        float mx0 = NEG_BIG, mx1 = NEG_BIG;
        #pragma unroll
        for (int j = 0; j < 8; j++) {
            mx0 = fmaxf(mx0, fmaxf(c[j][0], c[j][1]));
            mx1 = fmaxf(mx1, fmaxf(c[j][2], c[j][3]));
        }
        #pragma unroll
        for (int ox = 1; ox <= 2; ox <<= 1) {
            mx0 = fmaxf(mx0, __shfl_xor_sync(0xffffffffu, mx0, ox));
            mx1 = fmaxf(mx1, __shfl_xor_sync(0xffffffffu, mx1, ox));
        }
        float mn0 = fmaxf(m0, mx0), mn1 = fmaxf(m1, mx1);
        float corr0 = __expf(m0 - mn0), corr1 = __expf(m1 - mn1);
        m0 = mn0; m1 = mn1;

        float rs0 = 0.f, rs1 = 0.f;
        uint32_t aph[4][4], apl[4][4];
        #pragma unroll
        for (int j = 0; j < 8; j++) {
            float p00 = __expf(c[j][0] - mn0);
            float p01 = __expf(c[j][1] - mn0);
            float p10 = __expf(c[j][2] - mn1);
            float p11 = __expf(c[j][3] - mn1);
            rs0 += p00 + p01;
            rs1 += p10 + p11;
            int kc2 = j >> 1, sel = (j & 1) * 2;
            split2(p00, p01, aph[kc2][sel + 0], apl[kc2][sel + 0]);
            split2(p10, p11, aph[kc2][sel + 1], apl[kc2][sel + 1]);
        }
        #pragma unroll
        for (int ox = 1; ox <= 2; ox <<= 1) {
            rs0 += __shfl_xor_sync(0xffffffffu, rs0, ox);
            rs1 += __shfl_xor_sync(0xffffffffu, rs1, ox);
        }
        l0 = l0 * corr0 + rs0;
        l1 = l1 * corr1 + rs1;
        #pragma unroll
        for (int j = 0; j < 8; j++) {
            o[j][0] *= corr0; o[j][1] *= corr0;
            o[j][2] *= corr1; o[j][3] *= corr1;
        }

        // ---- O += P V (bf16 x3) ----
        #pragma unroll
        for (int kc2 = 0; kc2 < 4; kc2++) {
            #pragma unroll
            for (int up = 0; up < 4; up++) {
                int vrow = 16 * kc2 + (lane & 7) + ((lane >> 3) & 1) * 8;
                int vcol = 16 * up + (lane >> 4) * 8;
                uint32_t bvh[4], bvl[4];
                ldsm_x4_t(bvh, &sVh[vrow * STR + vcol]);
                ldsm_x4_t(bvl, &sVl[vrow * STR + vcol]);
                mma16816(o[2 * up],     aph[kc2], bvh[0], bvh[1]);
                mma16816(o[2 * up],     aph[kc2], bvl[0], bvl[1]);
                mma16816(o[2 * up],     apl[kc2], bvh[0], bvh[1]);
                mma16816(o[2 * up + 1], aph[kc2], bvh[2], bvh[3]);
                mma16816(o[2 * up + 1], aph[kc2], bvl[2], bvl[3]);
                mma16816(o[2 * up + 1], apl[kc2], bvh[2], bvh[3]);
            }
        }
    }

    // ---- epilogue ----
    float inv0 = 1.0f / l0, inv1 = 1.0f / l1;
    int rg = b * SEQ + q0 + w * 16 + (lane >> 2);
    #pragma unroll
    for (int j = 0; j < 8; j++) {
        int col = 8 * j + 2 * (lane & 3);
        float2 v0 = make_float2(o[j][0] * inv0, o[j][1] * inv0);
        float2 v1 = make_float2(o[j][2] * inv1, o[j][3] * inv1);
        *(float2*)&out[(size_t)rg * HDIM + col]       = v0;
        *(float2*)&out[(size_t)(rg + 8) * HDIM + col] = v1;
    }
}

// ---------------------------------------------------------------------------
extern "C" void kernel_launch(void* const* d_in, const int* in_sizes, int n_in,
                              void* d_out, int out_size)
{
    const float* x  = (const float*)d_in[0];
    const float* Wk = (const float*)d_in[1];
    const float* Wq = (const float*)d_in[2];
    const float* Wv = (const float*)d_in[3];
    float* out = (float*)d_out;

    dim3 ggrid(ROWS / 64, 3);
    qkv_gemm<<<ggrid, 256>>>(x, Wk, Wq, Wv);

    dim3 agrid(SEQ / BQ, BATCH);
    attn_kernel<<<agrid, 128>>>(out);
}

// round 5
// speedup vs baseline: 2.0052x; 1.2527x over previous
#include <cuda_runtime.h>
#include <cuda_bf16.h>
#include <cstdint>

// B=4, T=2048, E=768, H=64 — causal single-head attention, fp32 out.
// qkv_gemm_mma (bf16x3 tensor GEMM, in-kernel fp32->hi/lo split)
// + split-K fused flash attention (mma.sync bf16x3) + combine pass.

#define BATCH 4
#define SEQ   2048
#define EMB   768
#define HDIM  64
#define ROWS  (BATCH*SEQ)   // 8192

__device__ __nv_bfloat16 g_qh[ROWS*HDIM], g_ql[ROWS*HDIM];
__device__ __nv_bfloat16 g_kh[ROWS*HDIM], g_kl[ROWS*HDIM];
__device__ __nv_bfloat16 g_vh[ROWS*HDIM], g_vl[ROWS*HDIM];
// split-K attention partials (unnormalized O, running max m, sum l)
__device__ float g_pm[2][ROWS], g_pl[2][ROWS], g_po[2][ROWS*HDIM];

// ---------------- warp-mma helpers (sm_80+ baseline PTX) --------------------
__device__ __forceinline__ void ldsm_x4(uint32_t* r, const void* p) {
    uint32_t a = (uint32_t)__cvta_generic_to_shared(p);
    asm volatile("ldmatrix.sync.aligned.m8n8.x4.shared.b16 {%0,%1,%2,%3}, [%4];"
                 : "=r"(r[0]), "=r"(r[1]), "=r"(r[2]), "=r"(r[3]) : "r"(a));
}
__device__ __forceinline__ void ldsm_x4_t(uint32_t* r, const void* p) {
    uint32_t a = (uint32_t)__cvta_generic_to_shared(p);
    asm volatile("ldmatrix.sync.aligned.m8n8.x4.trans.shared.b16 {%0,%1,%2,%3}, [%4];"
                 : "=r"(r[0]), "=r"(r[1]), "=r"(r[2]), "=r"(r[3]) : "r"(a));
}
__device__ __forceinline__ void mma16816(float* c, const uint32_t* a,
                                         uint32_t b0, uint32_t b1) {
    asm volatile("mma.sync.aligned.m16n8k16.row.col.f32.bf16.bf16.f32 "
                 "{%0,%1,%2,%3}, {%4,%5,%6,%7}, {%8,%9}, {%0,%1,%2,%3};"
                 : "+f"(c[0]), "+f"(c[1]), "+f"(c[2]), "+f"(c[3])
                 : "r"(a[0]), "r"(a[1]), "r"(a[2]), "r"(a[3]), "r"(b0), "r"(b1));
}
__device__ __forceinline__ uint32_t pack_bf16x2(float lo, float hi) {
    uint32_t r;
    asm("cvt.rn.bf16x2.f32 %0, %1, %2;" : "=r"(r) : "f"(hi), "f"(lo));
    return r;
}
__device__ __forceinline__ void split2(float p0, float p1, uint32_t& hi, uint32_t& lo) {
    uint32_t h = pack_bf16x2(p0, p1);
    __nv_bfloat162 hb = *reinterpret_cast<__nv_bfloat162*>(&h);
    float2 hf = __bfloat1622float2(hb);
    lo = pack_bf16x2(p0 - hf.x, p1 - hf.y);
    hi = h;
}

// ---------------------------------------------------------------------------
// K1: QKV projection on tensor cores. CTA = 64 rows x 64 cols, one weight.
// A = x hi/lo, B = W hi/lo (split at smem-store time). C = Ah Bh + Al Bh + Ah Bl.
// ---------------------------------------------------------------------------
#define GSTR 72

__global__ __launch_bounds__(128)
void qkv_gemm_mma(const float* __restrict__ x,
                  const float* __restrict__ Wk,
                  const float* __restrict__ Wq,
                  const float* __restrict__ Wv)
{
    __shared__ __nv_bfloat16 sXh[64 * GSTR], sXl[64 * GSTR];
    __shared__ __nv_bfloat16 sWh[64 * GSTR], sWl[64 * GSTR];

    const float* W = (blockIdx.y == 0) ? Wq : (blockIdx.y == 1) ? Wk : Wv;
    const int m0   = blockIdx.x * 64;
    const int t    = threadIdx.x;
    const int w    = t >> 5;
    const int lane = t & 31;

    float c[8][4];
    #pragma unroll
    for (int j = 0; j < 8; j++)
        #pragma unroll
        for (int e = 0; e < 4; e++) c[j][e] = 0.f;

    const int lrow = (lane & 7) + ((lane >> 3) & 1) * 8;
    const int lcol = (lane >> 4) * 8;

    for (int kc0 = 0; kc0 < EMB; kc0 += 64) {
        __syncthreads();
        {   // x chunk: 64 rows x 64 k fp32 -> hi/lo bf16
            int row = t >> 1, half = t & 1;
            const float4* src = (const float4*)(x + (size_t)(m0 + row) * EMB + kc0 + half * 32);
            #pragma unroll
            for (int i = 0; i < 8; i++) {
                float4 v = src[i];
                int so = row * GSTR + half * 32 + i * 4;
                uint32_t h0, l0, h1, l1;
                split2(v.x, v.y, h0, l0);
                split2(v.z, v.w, h1, l1);
                *(uint32_t*)&sXh[so]     = h0;  *(uint32_t*)&sXh[so + 2] = h1;
                *(uint32_t*)&sXl[so]     = l0;  *(uint32_t*)&sXl[so + 2] = l1;
            }
        }
        {   // W chunk: 64 k-rows x 64 n fp32 -> hi/lo bf16
            int row = t >> 1, half = t & 1;
            const float4* src = (const float4*)(W + (size_t)(kc0 + row) * HDIM + half * 32);
            #pragma unroll
            for (int i = 0; i < 8; i++) {
                float4 v = src[i];
                int so = row * GSTR + half * 32 + i * 4;
                uint32_t h0, l0, h1, l1;
                split2(v.x, v.y, h0, l0);
                split2(v.z, v.w, h1, l1);
                *(uint32_t*)&sWh[so]     = h0;  *(uint32_t*)&sWh[so + 2] = h1;
                *(uint32_t*)&sWl[so]     = l0;  *(uint32_t*)&sWl[so + 2] = l1;
            }
        }
        __syncthreads();

        #pragma unroll
        for (int kc = 0; kc < 4; kc++) {
            uint32_t ah[4], al[4];
            ldsm_x4(ah, &sXh[(w * 16 + lrow) * GSTR + kc * 16 + lcol]);
            ldsm_x4(al, &sXl[(w * 16 + lrow) * GSTR + kc * 16 + lcol]);
            int krow = 16 * kc + (lane & 7) + ((lane >> 3) & 1) * 8;
            #pragma unroll
            for (int np = 0; np < 4; np++) {
                int ncol = 16 * np + (lane >> 4) * 8;
                uint32_t bh[4], bl[4];
                ldsm_x4_t(bh, &sWh[krow * GSTR + ncol]);
                ldsm_x4_t(bl, &sWl[krow * GSTR + ncol]);
                mma16816(c[2 * np],     ah, bh[0], bh[1]);
                mma16816(c[2 * np],     ah, bl[0], bl[1]);
                mma16816(c[2 * np],     al, bh[0], bh[1]);
                mma16816(c[2 * np + 1], ah, bh[2], bh[3]);
                mma16816(c[2 * np + 1], ah, bl[2], bl[3]);
                mma16816(c[2 * np + 1], al, bh[2], bh[3]);
            }
        }
    }

    const float sc = (blockIdx.y == 0) ? rsqrtf((float)EMB) : 1.0f;
    __nv_bfloat16* oh = (blockIdx.y == 0) ? g_qh : (blockIdx.y == 1) ? g_kh : g_vh;
    __nv_bfloat16* ol = (blockIdx.y == 0) ? g_ql : (blockIdx.y == 1) ? g_kl : g_vl;

    int r0 = m0 + w * 16 + (lane >> 2);
    #pragma unroll
    for (int j = 0; j < 8; j++) {
        int col = 8 * j + 2 * (lane & 3);
        uint32_t h, l;
        split2(c[j][0] * sc, c[j][1] * sc, h, l);
        *(uint32_t*)&oh[(size_t)r0 * HDIM + col] = h;
        *(uint32_t*)&ol[(size_t)r0 * HDIM + col] = l;
        split2(c[j][2] * sc, c[j][3] * sc, h, l);
        *(uint32_t*)&oh[(size_t)(r0 + 8) * HDIM + col] = h;
        *(uint32_t*)&ol[(size_t)(r0 + 8) * HDIM + col] = l;
    }
}

// ---------------------------------------------------------------------------
// K2: split-K fused flash attention. CTA = (q-tile of 64 rows, chunk in {0,1});
// chunk processes key-blocks kb = chunk, chunk+2, ... Writes unnormalized
// partials (O, m, l); combine pass merges.
// ---------------------------------------------------------------------------
#define BQ  64
#define BK  64
#define STR 72
#define NEG_BIG (-1e30f)

__global__ __launch_bounds__(128)
void attn_kernel()
{
    __shared__ __nv_bfloat16 sKh[BK * STR], sKl[BK * STR];
    __shared__ __nv_bfloat16 sVh[BK * STR], sVl[BK * STR];

    const int b     = blockIdx.y;
    const int tile  = blockIdx.x >> 1;    // 0..31
    const int chunk = blockIdx.x & 1;
    const int q0    = tile * BQ;
    const int t     = threadIdx.x;
    const int w     = t >> 5;
    const int lane  = t & 31;

    // ---- stage Q (hi/lo) through sKh/sKl into register A-frags ----
    {
        int row = t >> 1, half = t & 1;
        size_t g = (size_t)(b * SEQ + q0 + row) * HDIM + half * 32;
        const uint4* ph = (const uint4*)(g_qh + g);
        const uint4* pl = (const uint4*)(g_ql + g);
        #pragma unroll
        for (int i = 0; i < 4; i++) {
            *(uint4*)&sKh[row * STR + half * 32 + i * 8] = ph[i];
            *(uint4*)&sKl[row * STR + half * 32 + i * 8] = pl[i];
        }
    }
    __syncthreads();

    uint32_t qhf[4][4], qlf[4][4];
    {
        int lrow = (lane & 7) + ((lane >> 3) & 1) * 8;
        int lcol = (lane >> 4) * 8;
        #pragma unroll
        for (int kc = 0; kc < 4; kc++) {
            ldsm_x4(qhf[kc], &sKh[(w * 16 + lrow) * STR + kc * 16 + lcol]);
            ldsm_x4(qlf[kc], &sKl[(w * 16 + lrow) * STR + kc * 16 + lcol]);
        }
    }

    float m0 = NEG_BIG, m1 = NEG_BIG, l0 = 0.f, l1 = 0.f;
    float o[8][4];
    #pragma unroll
    for (int j = 0; j < 8; j++)
        #pragma unroll
        for (int e = 0; e < 4; e++) o[j][e] = 0.f;

    const int nkb = tile + 1;

    for (int kb = chunk; kb < nkb; kb += 2) {
        const int k0 = kb * BK;
        __syncthreads();
        {
            int row = t >> 1, half = t & 1;
            size_t g = (size_t)(b * SEQ + k0 + row) * HDIM + half * 32;
            const uint4* pkh = (const uint4*)(g_kh + g);
            const uint4* pkl = (const uint4*)(g_kl + g);
            const uint4* pvh = (const uint4*)(g_vh + g);
            const uint4* pvl = (const uint4*)(g_vl + g);
            #pragma unroll
            for (int i = 0; i < 4; i++) {
                int so = row * STR + half * 32 + i * 8;
                *(uint4*)&sKh[so] = pkh[i];
                *(uint4*)&sKl[so] = pkl[i];
                *(uint4*)&sVh[so] = pvh[i];
                *(uint4*)&sVl[so] = pvl[i];
            }
        }
        __syncthreads();

        // ---- S = Q K^T (bf16 x3) ----
        float c[8][4];
        #pragma unroll
        for (int j = 0; j < 8; j++)
            #pragma unroll
            for (int e = 0; e < 4; e++) c[j][e] = 0.f;

        #pragma unroll
        for (int kc = 0; kc < 4; kc++) {
            #pragma unroll
            for (int jp = 0; jp < 4; jp++) {
                int krow = 16 * jp + (lane & 7) + (lane >> 4) * 8;
                int kcol = kc * 16 + ((lane >> 3) & 1) * 8;
                uint32_t bh[4], bl[4];
                ldsm_x4(bh, &sKh[krow * STR + kcol]);
                ldsm_x4(bl, &sKl[krow * STR + kcol]);
                mma16816(c[2 * jp],     qhf[kc], bh[0], bh[1]);
                mma16816(c[2 * jp],     qhf[kc], bl[0], bl[1]);
                mma16816(c[2 * jp],     qlf[kc], bh[0], bh[1]);
                mma16816(c[2 * jp + 1], qhf[kc], bh[2], bh[3]);
                mma16816(c[2 * jp + 1], qhf[kc], bl[2], bl[3]);
                mma16816(c[2 * jp + 1], qlf[kc], bh[2], bh[3]);
            }
        }

        // ---- causal mask (diagonal block only) ----
        if (k0 == q0) {
            int r0g = q0 + w * 16 + (lane >> 2);
            #pragma unroll
            for (int j = 0; j < 8; j++) {
                int cg = k0 + 8 * j + 2 * (lane & 3);
                if (cg     > r0g)     c[j][0] = NEG_BIG;
                if (cg + 1 > r0g)     c[j][1] = NEG_BIG;
                if (cg     > r0g + 8) c[j][2] = NEG_BIG;
                if (cg + 1 > r0g + 8) c[j][3] = NEG_BIG;
            }
        }

        // ---- online softmax ----
        float mx0 = NEG_BIG, mx1 = NEG_BIG;
        #pragma unroll
        for (int j = 0; j < 8; j++) {
            mx0 = fmaxf(mx0, fmaxf(c[j][0], c[j][1]));
            mx1 = fmaxf(mx1, fmaxf(c[j][2], c[j][3]));
        }
        #pragma unroll
        for (int ox = 1; ox <= 2; ox <<= 1) {
            mx0 = fmaxf(mx0, __shfl_xor_sync(0xffffffffu, mx0, ox));
            mx1 = fmaxf(mx1, __shfl_xor_sync(0xffffffffu, mx1, ox));
        }
        float mn0 = fmaxf(m0, mx0), mn1 = fmaxf(m1, mx1);
        float corr0 = __expf(m0 - mn0), corr1 = __expf(m1 - mn1);
        m0 = mn0; m1 = mn1;

        float rs0 = 0.f, rs1 = 0.f;
        uint32_t aph[4][4], apl[4][4];
        #pragma unroll
        for (int j = 0; j < 8; j++) {
            float p00 = __expf(c[j][0] - mn0);
            float p01 = __expf(c[j][1] - mn0);
            float p10 = __expf(c[j][2] - mn1);
            float p11 = __expf(c[j][3] - mn1);
            rs0 += p00 + p01;
            rs1 += p10 + p11;
            int kc2 = j >> 1, sel = (j & 1) * 2;
            split2(p00, p01, aph[kc2][sel + 0], apl[kc2][sel + 0]);
            split2(p10, p11, aph[kc2][sel + 1], apl[kc2][sel + 1]);
        }
        #pragma unroll
        for (int ox = 1; ox <= 2; ox <<= 1) {
            rs0 += __shfl_xor_sync(0xffffffffu, rs0, ox);
            rs1 += __shfl_xor_sync(0xffffffffu, rs1, ox);
        }
        l0 = l0 * corr0 + rs0;
        l1 = l1 * corr1 + rs1;
        #pragma unroll
        for (int j = 0; j < 8; j++) {
            o[j][0] *= corr0; o[j][1] *= corr0;
            o[j][2] *= corr1; o[j][3] *= corr1;
        }

        // ---- O += P V (bf16 x3) ----
        #pragma unroll
        for (int kc2 = 0; kc2 < 4; kc2++) {
            #pragma unroll
            for (int up = 0; up < 4; up++) {
                int vrow = 16 * kc2 + (lane & 7) + ((lane >> 3) & 1) * 8;
                int vcol = 16 * up + (lane >> 4) * 8;
                uint32_t bvh[4], bvl[4];
                ldsm_x4_t(bvh, &sVh[vrow * STR + vcol]);
                ldsm_x4_t(bvl, &sVl[vrow * STR + vcol]);
                mma16816(o[2 * up],     aph[kc2], bvh[0], bvh[1]);
                mma16816(o[2 * up],     aph[kc2], bvl[0], bvl[1]);
                mma16816(o[2 * up],     apl[kc2], bvh[0], bvh[1]);
                mma16816(o[2 * up + 1], aph[kc2], bvh[2], bvh[3]);
                mma16816(o[2 * up + 1], aph[kc2], bvl[2], bvl[3]);
                mma16816(o[2 * up + 1], apl[kc2], bvh[2], bvh[3]);
            }
        }
    }

    // ---- write partials ----
    int rl0 = b * SEQ + q0 + w * 16 + (lane >> 2);
    if ((lane & 3) == 0) {
        g_pm[chunk][rl0]     = m0;  g_pl[chunk][rl0]     = l0;
        g_pm[chunk][rl0 + 8] = m1;  g_pl[chunk][rl0 + 8] = l1;
    }
    #pragma unroll
    for (int j = 0; j < 8; j++) {
        int col = 8 * j + 2 * (lane & 3);
        *(float2*)&g_po[chunk][(size_t)rl0 * HDIM + col]       = make_float2(o[j][0], o[j][1]);
        *(float2*)&g_po[chunk][(size_t)(rl0 + 8) * HDIM + col] = make_float2(o[j][2], o[j][3]);
    }
}

// ---------------------------------------------------------------------------
// K3: combine the two split-K partials.
// ---------------------------------------------------------------------------
__global__ __launch_bounds__(256)
void combine_kernel(float* __restrict__ out)
{
    int idx = blockIdx.x * 256 + threadIdx.x;   // over ROWS*32
    int row = idx >> 5;
    int col = (idx & 31) * 2;
    float m0 = g_pm[0][row], m1 = g_pm[1][row];
    float mx = fmaxf(m0, m1);
    float s0 = __expf(m0 - mx), s1 = __expf(m1 - mx);
    float l  = g_pl[0][row] * s0 + g_pl[1][row] * s1;
    float inv = 1.0f / l;
    float2 a = *(const float2*)&g_po[0][(size_t)row * HDIM + col];
    float2 bb = *(const float2*)&g_po[1][(size_t)row * HDIM + col];
    float2 r = make_float2((a.x * s0 + bb.x * s1) * inv,
                           (a.y * s0 + bb.y * s1) * inv);
    *(float2*)&out[(size_t)row * HDIM + col] = r;
}

// ---------------------------------------------------------------------------
extern "C" void kernel_launch(void* const* d_in, const int* in_sizes, int n_in,
                              void* d_out, int out_size)
{
    const float* x  = (const float*)d_in[0];
    const float* Wk = (const float*)d_in[1];
    const float* Wq = (const float*)d_in[2];
    const float* Wv = (const float*)d_in[3];
    float* out = (float*)d_out;

    dim3 ggrid(ROWS / 64, 3);
    qkv_gemm_mma<<<ggrid, 128>>>(x, Wk, Wq, Wv);

    dim3 agrid((SEQ / BQ) * 2, BATCH);
    attn_kernel<<<agrid, 128>>>();

    combine_kernel<<<(ROWS * 32) / 256, 256>>>(out);
}